// round 2
// baseline (speedup 1.0000x reference)
#include <cuda_runtime.h>
#include <cstdint>

#define FULL_MASK 0xFFFFFFFFu

// Fast sigmoid returning both s = sigmoid(z) and oms = 1 - s (exactly complementary).
__device__ __forceinline__ void sigmoid_pair(float z, float& s, float& oms) {
    float e   = __expf(-z);
    float inv = __fdividef(1.0f, 1.0f + e);
    s   = inv;
    oms = e * inv;
}

__device__ __forceinline__ float sigmoid1(float z) {
    float e = __expf(-z);
    return __fdividef(1.0f, 1.0f + e);
}

// Streaming (evict-first) 16B store: sigma output is write-only, keep it out of L2
// so the grid-table gathers retain more cache.
__device__ __forceinline__ void store_cs_f4(float4* p, float4 v) {
    asm volatile("st.global.cs.v4.f32 [%0], {%1,%2,%3,%4};"
                 :: "l"(p), "f"(v.x), "f"(v.y), "f"(v.z), "f"(v.w) : "memory");
}

// ---------------------------------------------------------------------------
// Main kernel: one warp per ray. Lane L owns samples [L*SPL, (L+1)*SPL).
// SPL = N / 32 (compile-time).
// Output layout: out[0 : B*N] = sigma (row-major [B,N]), out[B*N : B*N+3B] = rgb.
// ---------------------------------------------------------------------------
template <int SPL>
__global__ __launch_bounds__(256)
void surf_warp_kernel(const int* __restrict__ x,
                      const float* __restrict__ d,
                      const float4* __restrict__ grid,   // [TABLE] rows of 4 floats
                      const float* __restrict__ W0,      // [22, 8] row-major
                      const float* __restrict__ W1,      // [8, 3] row-major
                      float* __restrict__ out,
                      int B, int N)
{
    const int gwarp = (blockIdx.x * blockDim.x + threadIdx.x) >> 5;
    const int lane  = threadIdx.x & 31;
    if (gwarp >= B) return;
    const int b = gwarp;

    // ---- load weights into registers (float4 vectorized; warp-uniform -> L1 hits)
    float w0g[6][8];   // W0 rows 16..21 (geo part)
    {
        const float4* p = reinterpret_cast<const float4*>(W0 + 16 * 8);
        #pragma unroll
        for (int k = 0; k < 6; ++k) {
            float4 a = __ldg(p + 2 * k);
            float4 c = __ldg(p + 2 * k + 1);
            w0g[k][0] = a.x; w0g[k][1] = a.y; w0g[k][2] = a.z; w0g[k][3] = a.w;
            w0g[k][4] = c.x; w0g[k][5] = c.y; w0g[k][6] = c.z; w0g[k][7] = c.w;
        }
    }
    float w1[24];      // W1 [8,3]
    {
        const float4* p = reinterpret_cast<const float4*>(W1);
        #pragma unroll
        for (int q = 0; q < 6; ++q) {
            float4 a = __ldg(p + q);
            w1[4 * q + 0] = a.x; w1[4 * q + 1] = a.y;
            w1[4 * q + 2] = a.z; w1[4 * q + 3] = a.w;
        }
    }

    // ---- per-ray invariant: dbase[j] = sum_k d[b,k] * W0[k,j]  (k < 16)
    // Lanes 0..7 each compute one column, then broadcast.
    float dbase[8];
    {
        float acc = 0.0f;
        if (lane < 8) {
            const float* dr = d + (size_t)b * 16;
            #pragma unroll
            for (int k = 0; k < 16; ++k)
                acc = fmaf(__ldg(dr + k), __ldg(W0 + k * 8 + lane), acc);
        }
        #pragma unroll
        for (int j = 0; j < 8; ++j)
            dbase[j] = __shfl_sync(FULL_MASK, acc, j);
    }

    const int n0 = lane * SPL;

    // ---- load indices (2*SPL consecutive ints, 8B-aligned -> int2)
    int idx[2 * SPL];
    {
        const int2* xp = reinterpret_cast<const int2*>(x + (size_t)b * N * 2 + n0 * 2);
        #pragma unroll
        for (int q = 0; q < SPL; ++q) {
            int2 v = __ldg(xp + q);
            idx[2 * q]     = v.x;
            idx[2 * q + 1] = v.y;
        }
    }

    // ---- issue all gathers up front (MLP = 2*SPL per lane)
    float4 f0[SPL], f1[SPL];
    #pragma unroll
    for (int i = 0; i < SPL; ++i) {
        f0[i] = __ldg(grid + idx[2 * i]);
        f1[i] = __ldg(grid + idx[2 * i + 1]);
    }

    // ---- per-sample MLP
    float sig[SPL], oms[SPL];
    float col[SPL][3];
    #pragma unroll
    for (int i = 0; i < SPL; ++i) {
        sigmoid_pair(f0[i].x * f1[i].x, sig[i], oms[i]);

        float h[8];
        #pragma unroll
        for (int j = 0; j < 8; ++j) {
            float v = dbase[j];
            v = fmaf(f0[i].y, w0g[0][j], v);
            v = fmaf(f0[i].z, w0g[1][j], v);
            v = fmaf(f0[i].w, w0g[2][j], v);
            v = fmaf(f1[i].y, w0g[3][j], v);
            v = fmaf(f1[i].z, w0g[4][j], v);
            v = fmaf(f1[i].w, w0g[5][j], v);
            h[j] = fmaxf(v, 0.0f);
        }
        #pragma unroll
        for (int m = 0; m < 3; ++m) {
            float c = 0.0f;
            #pragma unroll
            for (int j = 0; j < 8; ++j)
                c = fmaf(h[j], w1[j * 3 + m], c);
            col[i][m] = sigmoid1(c);
        }
    }

    // ---- store sigma (coalesced; streaming float4 when possible)
    if constexpr (SPL % 4 == 0) {
        float4* o4 = reinterpret_cast<float4*>(out + (size_t)b * N + n0);
        #pragma unroll
        for (int q = 0; q < SPL / 4; ++q) {
            float4 v;
            v.x = sig[4 * q + 0]; v.y = sig[4 * q + 1];
            v.z = sig[4 * q + 2]; v.w = sig[4 * q + 3];
            store_cs_f4(o4 + q, v);
        }
    } else {
        #pragma unroll
        for (int i = 0; i < SPL; ++i)
            out[(size_t)b * N + n0 + i] = sig[i];
    }

    // ---- transmittance: cumprod of (1 - sigma), exclusive (shifted by one)
    float pref[SPL];
    float p = 1.0f;
    #pragma unroll
    for (int i = 0; i < SPL; ++i) {
        pref[i] = p;
        p *= oms[i];
    }
    // inclusive product scan across lanes
    float inc = p;
    #pragma unroll
    for (int off = 1; off < 32; off <<= 1) {
        float v = __shfl_up_sync(FULL_MASK, inc, off);
        if (lane >= off) inc *= v;
    }
    float excl = __shfl_up_sync(FULL_MASK, inc, 1);
    if (lane == 0) excl = 1.0f;

    // ---- weighted rgb accumulation + warp reduce
    float r0 = 0.0f, r1 = 0.0f, r2 = 0.0f;
    #pragma unroll
    for (int i = 0; i < SPL; ++i) {
        float w = excl * pref[i] * sig[i];
        r0 = fmaf(w, col[i][0], r0);
        r1 = fmaf(w, col[i][1], r1);
        r2 = fmaf(w, col[i][2], r2);
    }
    #pragma unroll
    for (int off = 16; off; off >>= 1) {
        r0 += __shfl_xor_sync(FULL_MASK, r0, off);
        r1 += __shfl_xor_sync(FULL_MASK, r1, off);
        r2 += __shfl_xor_sync(FULL_MASK, r2, off);
    }
    if (lane == 0) {
        float* rgb = out + (size_t)B * N + (size_t)b * 3;
        rgb[0] = r0; rgb[1] = r1; rgb[2] = r2;
    }
}

// ---------------------------------------------------------------------------
// Fallback: one thread per ray, sequential over N (any N). Correct but slow.
// ---------------------------------------------------------------------------
__global__ void surf_fallback_kernel(const int* __restrict__ x,
                                     const float* __restrict__ d,
                                     const float4* __restrict__ grid,
                                     const float* __restrict__ W0,
                                     const float* __restrict__ W1,
                                     float* __restrict__ out,
                                     int B, int N)
{
    int b = blockIdx.x * blockDim.x + threadIdx.x;
    if (b >= B) return;

    float dbase[8];
    #pragma unroll
    for (int j = 0; j < 8; ++j) {
        float acc = 0.0f;
        for (int k = 0; k < 16; ++k)
            acc = fmaf(d[(size_t)b * 16 + k], W0[k * 8 + j], acc);
        dbase[j] = acc;
    }

    float T = 1.0f;
    float r0 = 0.0f, r1 = 0.0f, r2 = 0.0f;
    for (int n = 0; n < N; ++n) {
        int i0 = x[((size_t)b * N + n) * 2 + 0];
        int i1 = x[((size_t)b * N + n) * 2 + 1];
        float4 f0 = __ldg(grid + i0);
        float4 f1 = __ldg(grid + i1);
        float s, om;
        sigmoid_pair(f0.x * f1.x, s, om);
        out[(size_t)b * N + n] = s;

        float h[8];
        #pragma unroll
        for (int j = 0; j < 8; ++j) {
            float v = dbase[j];
            v = fmaf(f0.y, W0[16 * 8 + j], v);
            v = fmaf(f0.z, W0[17 * 8 + j], v);
            v = fmaf(f0.w, W0[18 * 8 + j], v);
            v = fmaf(f1.y, W0[19 * 8 + j], v);
            v = fmaf(f1.z, W0[20 * 8 + j], v);
            v = fmaf(f1.w, W0[21 * 8 + j], v);
            h[j] = fmaxf(v, 0.0f);
        }
        float c[3];
        #pragma unroll
        for (int m = 0; m < 3; ++m) {
            float acc = 0.0f;
            #pragma unroll
            for (int j = 0; j < 8; ++j)
                acc = fmaf(h[j], W1[j * 3 + m], acc);
            c[m] = sigmoid1(acc);
        }
        float w = T * s;
        r0 = fmaf(w, c[0], r0);
        r1 = fmaf(w, c[1], r1);
        r2 = fmaf(w, c[2], r2);
        T *= om;
    }
    float* rgb = out + (size_t)B * N + (size_t)b * 3;
    rgb[0] = r0; rgb[1] = r1; rgb[2] = r2;
}

// ---------------------------------------------------------------------------
// kernel_launch
// Inputs (metadata order): x (int32 [B,N,2]), d (f32 [B,16]),
//   gridWeight (f32 [TABLE,4]), W0 (f32 [22,8]), W1 (f32 [8,3]).
// Output: float32, [sigma (B*N) | rgb (B*3)].
// ---------------------------------------------------------------------------
extern "C" void kernel_launch(void* const* d_in, const int* in_sizes, int n_in,
                              void* d_out, int out_size)
{
    const int*    x    = (const int*)d_in[0];
    const float*  d    = (const float*)d_in[1];
    const float4* grid = (const float4*)d_in[2];
    const float*  W0   = (const float*)d_in[3];
    const float*  W1   = (const float*)d_in[4];
    float*        out  = (float*)d_out;

    const int B = in_sizes[1] / 16;                 // d is [B, 16]
    const int N = in_sizes[0] / (2 * B);            // x is [B, N, 2]

    if (N % 32 == 0) {
        const int spl = N / 32;
        const int threads = 256;                    // 8 warps/block
        const int blocks  = (B * 32 + threads - 1) / threads;
        switch (spl) {
            case 1: surf_warp_kernel<1><<<blocks, threads>>>(x, d, grid, W0, W1, out, B, N); return;
            case 2: surf_warp_kernel<2><<<blocks, threads>>>(x, d, grid, W0, W1, out, B, N); return;
            case 4: surf_warp_kernel<4><<<blocks, threads>>>(x, d, grid, W0, W1, out, B, N); return;
            case 8: surf_warp_kernel<8><<<blocks, threads>>>(x, d, grid, W0, W1, out, B, N); return;
            default: break;
        }
    }
    // generic fallback
    const int threads = 128;
    const int blocks  = (B + threads - 1) / threads;
    surf_fallback_kernel<<<blocks, threads>>>(x, d, grid, W0, W1, out, B, N);
}